// round 1
// baseline (speedup 1.0000x reference)
#include <cuda_runtime.h>
#include <math.h>

// Problem constants (fixed for this problem instance)
#define NSPK   1024
#define MUTT   32
#define DEMB   512
#define NMROWS (NSPK * MUTT)   // 32768

// Tiling for the fused GEMM + logsumexp kernel
#define BM 64
#define BN 64
#define BK 16
#define GBLK   (NMROWS / BM)   // 512 blocks
#define NCHUNK (NSPK / BN)     // 16 column chunks

// Scratch (device globals; no allocation allowed in kernel_launch)
__device__ float g_centroid[NSPK * DEMB];  // 2 MB
__device__ float g_dval[NMROWS];           // 128 KB  (fp64-accurate diagonal values)
__device__ float g_part[GBLK];             // per-block partial loss sums

// ---------------------------------------------------------------------------
// Kernel 1: centroids  C[n,d] = (1/M) * sum_m e[n,m,d]
// One block per speaker. Division by 32 is exact (power of two), so
// 32*C == S (the raw sum) bit-exactly, which dval_kernel relies on.
// ---------------------------------------------------------------------------
__global__ __launch_bounds__(256) void centroid_kernel(const float* __restrict__ emb)
{
    const int n = blockIdx.x;
    const float* base = emb + (size_t)n * MUTT * DEMB;
    for (int d = threadIdx.x; d < DEMB; d += blockDim.x) {
        float s = 0.f;
        #pragma unroll
        for (int m = 0; m < MUTT; ++m) s += base[m * DEMB + d];
        g_centroid[n * DEMB + d] = s * (1.0f / MUTT);
    }
}

// ---------------------------------------------------------------------------
// Kernel 2: per-row diagonal value in fp64:
//   dval[r] = dot(e_r, S_spk) + ||e_r||^2 / 31
// (reference: diag = einsum(e, sum) - (1/(1-M)) * ||e||^2, 1/(1-32) = -1/31)
// One warp per row.
// ---------------------------------------------------------------------------
__global__ __launch_bounds__(256) void dval_kernel(const float* __restrict__ emb)
{
    const int warp = threadIdx.x >> 5;
    const int lane = threadIdx.x & 31;
    const int r    = blockIdx.x * 8 + warp;
    const int spk  = r >> 5;  // r / MUTT

    const float* e = emb + (size_t)r * DEMB;
    const float* c = g_centroid + (size_t)spk * DEMB;

    double dot = 0.0, nn = 0.0;
    #pragma unroll
    for (int k = 0; k < DEMB / 32; ++k) {
        float ev = e[lane + 32 * k];
        float Sd = c[lane + 32 * k] * (float)MUTT;  // exact: S = 32*C
        dot += (double)ev * (double)Sd;
        nn  += (double)ev * (double)ev;
    }
    #pragma unroll
    for (int o = 16; o; o >>= 1) {
        dot += __shfl_down_sync(0xffffffffu, dot, o);
        nn  += __shfl_down_sync(0xffffffffu, nn,  o);
    }
    if (lane == 0) g_dval[r] = (float)(dot + nn / 31.0);
}

// ---------------------------------------------------------------------------
// Kernel 3: fused GEMM (logits = w * (e @ C^T) + b, with diagonal overwrite)
//           + online row-wise logsumexp + per-block loss partial.
// Block: 256 threads = 16x16; each thread owns a 4x4 micro-tile of a
// BM x BN = 64x64 output tile. The 16 threads sharing a row-group reduce
// max / sumexp with shfl_xor over their contiguous 16-lane subgroup.
// ---------------------------------------------------------------------------
__global__ __launch_bounds__(256, 2) void main_kernel(const float* __restrict__ emb,
                                                      const float* __restrict__ wp,
                                                      const float* __restrict__ bp)
{
    __shared__ float As[BK][BM + 4];   // +4 pad: conflict mitigation, keeps 16B align
    __shared__ float Bs[BK][BN + 4];
    __shared__ float red[256];

    const int tid = threadIdx.x;
    const int tx  = tid & 15;
    const int ty  = tid >> 4;
    const int r0  = blockIdx.x * BM;

    const float wv = wp[0];
    const float bv = bp[0];

    // cooperative tile-load indices: each thread loads one float4 of A and B
    const int lr = tid >> 2;         // 0..63 : row within tile
    const int lc = (tid & 3) * 4;    // 0,4,8,12 : k-offset within BK

    float mx[4], s[4];
    #pragma unroll
    for (int i = 0; i < 4; ++i) { mx[i] = -INFINITY; s[i] = 0.f; }
    float diag_acc = 0.f;

    for (int cb = 0; cb < NCHUNK; ++cb) {
        float acc[4][4];
        #pragma unroll
        for (int i = 0; i < 4; ++i)
            #pragma unroll
            for (int j = 0; j < 4; ++j) acc[i][j] = 0.f;

        for (int kt = 0; kt < DEMB; kt += BK) {
            float4 ga = *(const float4*)(emb + (size_t)(r0 + lr) * DEMB + kt + lc);
            float4 gb = *(const float4*)(g_centroid + (size_t)(cb * BN + lr) * DEMB + kt + lc);
            __syncthreads();
            As[lc + 0][lr] = ga.x; As[lc + 1][lr] = ga.y;
            As[lc + 2][lr] = ga.z; As[lc + 3][lr] = ga.w;
            Bs[lc + 0][lr] = gb.x; Bs[lc + 1][lr] = gb.y;
            Bs[lc + 2][lr] = gb.z; Bs[lc + 3][lr] = gb.w;
            __syncthreads();
            #pragma unroll
            for (int k = 0; k < BK; ++k) {
                float4 av = *(const float4*)&As[k][ty * 4];
                float4 bq = *(const float4*)&Bs[k][tx * 4];
                float a[4] = {av.x, av.y, av.z, av.w};
                float bb[4] = {bq.x, bq.y, bq.z, bq.w};
                #pragma unroll
                for (int i = 0; i < 4; ++i)
                    #pragma unroll
                    for (int j = 0; j < 4; ++j)
                        acc[i][j] = fmaf(a[i], bb[j], acc[i][j]);
            }
        }

        // online logsumexp update for this 64-column chunk
        #pragma unroll
        for (int i = 0; i < 4; ++i) {
            const int row = r0 + ty * 4 + i;
            const int spk = row >> 5;
            float v[4];
            float vm = -INFINITY;
            #pragma unroll
            for (int j = 0; j < 4; ++j) {
                const int col = cb * BN + tx * 4 + j;
                float lg;
                if (col == spk) {
                    lg = fmaf(wv, g_dval[row], bv);   // diagonal overwrite
                    diag_acc += lg;                   // label logit (subtract later)
                } else {
                    lg = fmaf(wv, acc[i][j], bv);
                }
                v[j] = lg;
                vm = fmaxf(vm, lg);
            }
            // reduce over the 16 lanes that share this row (contiguous 16-lane group)
            #pragma unroll
            for (int o = 8; o; o >>= 1)
                vm = fmaxf(vm, __shfl_xor_sync(0xffffffffu, vm, o));
            const float nm = fmaxf(mx[i], vm);
            float sl = 0.f;
            #pragma unroll
            for (int j = 0; j < 4; ++j) sl += __expf(v[j] - nm);
            #pragma unroll
            for (int o = 8; o; o >>= 1)
                sl += __shfl_xor_sync(0xffffffffu, sl, o);
            s[i]  = s[i] * __expf(mx[i] - nm) + sl;
            mx[i] = nm;
        }
    }

    // per-thread partial: logsumexp from one lane per row group, minus diag logits
    float part = -diag_acc;
    if (tx == 0) {
        #pragma unroll
        for (int i = 0; i < 4; ++i) part += mx[i] + logf(s[i]);
    }

    __syncthreads();
    red[tid] = part;
    __syncthreads();
    #pragma unroll
    for (int st = 128; st; st >>= 1) {
        if (tid < st) red[tid] += red[tid + st];
        __syncthreads();
    }
    if (tid == 0) g_part[blockIdx.x] = red[0];
}

// ---------------------------------------------------------------------------
// Kernel 4: deterministic fixed-order final reduction -> mean
// ---------------------------------------------------------------------------
__global__ __launch_bounds__(256) void finish_kernel(float* __restrict__ out)
{
    __shared__ float red[256];
    const int tid = threadIdx.x;
    red[tid] = g_part[tid] + g_part[tid + 256];
    __syncthreads();
    #pragma unroll
    for (int st = 128; st; st >>= 1) {
        if (tid < st) red[tid] += red[tid + st];
        __syncthreads();
    }
    if (tid == 0) out[0] = red[0] * (1.0f / NMROWS);
}

// ---------------------------------------------------------------------------
// kernel_launch: graph-capturable, allocation-free, deterministic.
// Inputs (metadata order): embeddings[f32 16777216], w[f32 1], b[f32 1], N, M
// ---------------------------------------------------------------------------
extern "C" void kernel_launch(void* const* d_in, const int* in_sizes, int n_in,
                              void* d_out, int out_size)
{
    const float* emb = (const float*)d_in[0];
    const float* w   = (const float*)d_in[1];
    const float* b   = (const float*)d_in[2];
    float* out = (float*)d_out;

    centroid_kernel<<<NSPK, 256>>>(emb);
    dval_kernel<<<NMROWS / 8, 256>>>(emb);
    main_kernel<<<GBLK, 256>>>(emb, w, b);
    finish_kernel<<<1, 256>>>(out);
}

// round 3
// speedup vs baseline: 3.0130x; 3.0130x over previous
#include <cuda_runtime.h>
#include <cuda_bf16.h>
#include <cstdint>
#include <math.h>

// ---------------- problem constants ----------------
#define NSPK   1024
#define MUTT   32
#define DEMB   512
#define NMROWS (NSPK * MUTT)        // 32768
#define KSPLIT (3 * DEMB)           // 1536 bf16 (3-term split: hi*hi + hi*lo + lo*hi)

#define TM     64                   // CTA row tile
#define TNB    128                  // N chunk
#define NNB    (NSPK / TNB)         // 8
#define NKB    (KSPLIT / 64)        // 24 k64 chunks
#define NITER  (NNB * NKB)          // 192
#define GBLK   (NMROWS / TM)        // 512 CTAs

#define A_BYTES  (TM * 128)         // 8 KB  (64 rows x 64 bf16)
#define B_BYTES  (TNB * 128)        // 16 KB (128 rows x 64 bf16)
#define STAGE    (A_BYTES + B_BYTES)
#define SMEM_TOTAL (2 * STAGE)      // 49152

// ---------------- device scratch ----------------
__device__ __align__(1024) __nv_bfloat16 g_A2[(size_t)NMROWS * KSPLIT]; // 96 MB
__device__ __align__(1024) __nv_bfloat16 g_B2[(size_t)NSPK * KSPLIT];   // 3 MB
__device__ float g_dval[NMROWS];
__device__ float g_part[GBLK];

// ---------------- helpers ----------------
__device__ __forceinline__ uint32_t smem_u32(const void* p) {
    uint32_t a;
    asm("{ .reg .u64 t; cvta.to.shared.u64 t, %1; cvt.u32.u64 %0, t; }" : "=r"(a) : "l"(p));
    return a;
}
__device__ __forceinline__ void cp16(uint32_t s, const void* g) {
    asm volatile("cp.async.cg.shared.global [%0], [%1], 16;" :: "r"(s), "l"(g) : "memory");
}
__device__ __forceinline__ void ldsm4(uint32_t& r0, uint32_t& r1, uint32_t& r2, uint32_t& r3,
                                      uint32_t a) {
    asm volatile("ldmatrix.sync.aligned.m8n8.x4.shared.b16 {%0,%1,%2,%3}, [%4];"
                 : "=r"(r0), "=r"(r1), "=r"(r2), "=r"(r3) : "r"(a));
}
__device__ __forceinline__ void mma16816(float* c, uint32_t a0, uint32_t a1, uint32_t a2,
                                         uint32_t a3, uint32_t b0, uint32_t b1) {
    asm volatile(
        "mma.sync.aligned.m16n8k16.row.col.f32.bf16.bf16.f32 "
        "{%0,%1,%2,%3},{%4,%5,%6,%7},{%8,%9},{%0,%1,%2,%3};"
        : "+f"(c[0]), "+f"(c[1]), "+f"(c[2]), "+f"(c[3])
        : "r"(a0), "r"(a1), "r"(a2), "r"(a3), "r"(b0), "r"(b1));
}

// ---------------------------------------------------------------------------
// Prologue: per speaker n — centroid sum S, B2=[hi(C),lo(C),hi(C)],
// A2=[hi(e),hi(e),lo(e)], dval[r] = dot(e_r,S) + ||e_r||^2/31 (fp32 Kahan)
// ---------------------------------------------------------------------------
__global__ __launch_bounds__(256) void prologue_kernel(const float* __restrict__ emb)
{
    __shared__ float S[DEMB];
    const int n = blockIdx.x, tid = threadIdx.x;
    const float* base = emb + (size_t)n * MUTT * DEMB;

    for (int d = tid; d < DEMB; d += 256) {
        float s = 0.f;
        #pragma unroll
        for (int m = 0; m < MUTT; ++m) s += base[m * DEMB + d];
        S[d] = s;
        float cv = s * (1.0f / MUTT);
        __nv_bfloat16 hi = __float2bfloat16(cv);
        __nv_bfloat16 lo = __float2bfloat16(cv - __bfloat162float(hi));
        size_t o = (size_t)n * KSPLIT + d;
        g_B2[o] = hi; g_B2[o + DEMB] = lo; g_B2[o + 2 * DEMB] = hi;
    }
    __syncthreads();

    const int wid = tid >> 5, lane = tid & 31;
    #pragma unroll
    for (int rr = 0; rr < 4; ++rr) {
        const int m = wid + rr * 8;
        const float* e = base + m * DEMB;
        float dot = 0.f, cd = 0.f, nn = 0.f, cn = 0.f;
        for (int k = lane; k < DEMB; k += 32) {
            float ev = e[k];
            float x = ev * S[k];
            float y = x - cd; float t = dot + y; cd = (t - dot) - y; dot = t;
            float x2 = ev * ev;
            float y2 = x2 - cn; float t2 = nn + y2; cn = (t2 - nn) - y2; nn = t2;
        }
        #pragma unroll
        for (int o = 16; o; o >>= 1) {
            dot += __shfl_xor_sync(0xffffffffu, dot, o);
            nn  += __shfl_xor_sync(0xffffffffu, nn,  o);
        }
        if (lane == 0) g_dval[n * MUTT + m] = dot + nn * (1.0f / 31.0f);
    }

    for (int idx = tid; idx < MUTT * DEMB; idx += 256) {
        float x = base[idx];
        int m = idx >> 9, d = idx & (DEMB - 1);
        __nv_bfloat16 hi = __float2bfloat16(x);
        __nv_bfloat16 lo = __float2bfloat16(x - __bfloat162float(hi));
        size_t a = ((size_t)(n * MUTT + m)) * KSPLIT + d;
        g_A2[a] = hi; g_A2[a + DEMB] = hi; g_A2[a + 2 * DEMB] = lo;
    }
}

// ---------------------------------------------------------------------------
// Main: mma.sync bf16 GEMM + fused shifted online logsumexp
// 4 warps, each warp owns m16 x n128 (complete rows -> in-warp LSE).
// ---------------------------------------------------------------------------
__device__ __forceinline__ void load_tiles(int t, int m0, uint32_t sb, int tid)
{
    const int nb = t / NKB, kb = t - nb * NKB;
    const uint32_t st = (uint32_t)(t & 1) * STAGE;
    const char* gA = (const char*)g_A2 + (size_t)m0 * 3072 + kb * 128;
    const char* gB = (const char*)g_B2 + (size_t)nb * TNB * 3072 + kb * 128;
    #pragma unroll
    for (int i = 0; i < 4; ++i) {           // A: 512 x 16B
        int u = tid + i * 128;
        int r = u >> 3, c = u & 7;
        cp16(sb + st + r * 128 + (((c ^ (r & 7))) << 4),
             gA + (size_t)r * 3072 + c * 16);
    }
    #pragma unroll
    for (int i = 0; i < 8; ++i) {           // B: 1024 x 16B
        int u = tid + i * 128;
        int r = u >> 3, c = u & 7;
        cp16(sb + st + A_BYTES + r * 128 + (((c ^ (r & 7))) << 4),
             gB + (size_t)r * 3072 + c * 16);
    }
}

__global__ __launch_bounds__(128, 4) void main_kernel(const float* __restrict__ wp)
{
    extern __shared__ __align__(128) char smem[];
    const uint32_t sb = smem_u32(smem);
    __shared__ float red[4];

    const int tid = threadIdx.x, wid = tid >> 5, lane = tid & 31;
    const int q = lane >> 2, r4 = lane & 3;
    const int m0 = blockIdx.x * TM;

    const float wv   = wp[0];
    const int   R0   = m0 + wid * 16 + q;        // thread's row pair: R0, R0+8
    const float wdv0 = wv * g_dval[R0];
    const float wdv1 = wv * g_dval[R0 + 8];
    const int   spkcol = R0 >> 5;                // same speaker for both rows

    // ldsm row/chunk pieces (same pattern for A and B)
    const int lrow  = lane & 15;                 // row within 16-row group
    const int lkoff = lane >> 4;                 // k-chunk half select

    float acc[16][4];
    float mM[2] = {-INFINITY, -INFINITY}, sS[2] = {0.f, 0.f};

    load_tiles(0, m0, sb, tid);
    asm volatile("cp.async.commit_group;" ::: "memory");

    for (int t = 0; t < NITER; ++t) {
        const int nb = t / NKB, kb = t - nb * NKB;

        if (t + 1 < NITER) {
            load_tiles(t + 1, m0, sb, tid);
            asm volatile("cp.async.commit_group;" ::: "memory");
            asm volatile("cp.async.wait_group 1;" ::: "memory");
        } else {
            asm volatile("cp.async.wait_group 0;" ::: "memory");
        }
        __syncthreads();

        if (kb == 0) {
            #pragma unroll
            for (int j = 0; j < 16; ++j)
                #pragma unroll
                for (int e = 0; e < 4; ++e) acc[j][e] = 0.f;
        }

        const uint32_t st = sb + (uint32_t)(t & 1) * STAGE;
        #pragma unroll
        for (int ks = 0; ks < 4; ++ks) {
            uint32_t a0, a1, a2, a3;
            {
                int r = wid * 16 + lrow;
                int c = ks * 2 + lkoff;
                ldsm4(a0, a1, a2, a3, st + r * 128 + (((c ^ (r & 7))) << 4));
            }
            #pragma unroll
            for (int g = 0; g < 8; ++g) {        // n16 groups
                uint32_t b0, b1, b2, b3;
                int r = g * 16 + lrow;
                int c = ks * 2 + lkoff;
                ldsm4(b0, b1, b2, b3,
                      st + A_BYTES + r * 128 + (((c ^ (r & 7))) << 4));
                mma16816(acc[2 * g + 0], a0, a1, a2, a3, b0, b2);
                mma16816(acc[2 * g + 1], a0, a1, a2, a3, b1, b3);
            }
        }

        if (kb == NKB - 1) {
            // shifted online LSE over this 128-col chunk
            #pragma unroll
            for (int h = 0; h < 2; ++h) {
                float m = mM[h], s = sS[h];
                const float wdv = h ? wdv1 : wdv0;
                #pragma unroll
                for (int j = 0; j < 16; ++j) {
                    #pragma unroll
                    for (int e = 0; e < 2; ++e) {
                        const int col = nb * 128 + j * 8 + r4 * 2 + e;
                        if (col != spkcol) {
                            float v = fmaf(wv, acc[j][h * 2 + e], -wdv);
                            if (v > m) { s = s * __expf(m - v) + 1.f; m = v; }
                            else { float d = v - m; if (d > -80.f) s += __expf(d); }
                        }
                    }
                }
                mM[h] = m; sS[h] = s;
            }
        }
        __syncthreads();
    }

    // quad merge (lanes sharing a row differ in r4 = bits 0..1), then diag term
    #pragma unroll
    for (int h = 0; h < 2; ++h) {
        float m = mM[h], s = sS[h];
        #pragma unroll
        for (int o = 1; o <= 2; o <<= 1) {
            float om = __shfl_xor_sync(0xffffffffu, m, o);
            float os = __shfl_xor_sync(0xffffffffu, s, o);
            float nm = fmaxf(m, om);
            s = s * __expf(m - nm) + os * __expf(om - nm);
            m = nm;
        }
        float nm = fmaxf(m, 0.f);                // merge diagonal (v=0, weight 1)
        s = s * __expf(m - nm) + __expf(-nm);
        mM[h] = nm; sS[h] = s;
    }
    float contrib = (r4 == 0)
        ? (mM[0] + logf(sS[0]) + mM[1] + logf(sS[1])) : 0.f;
    #pragma unroll
    for (int o = 16; o; o >>= 1)
        contrib += __shfl_xor_sync(0xffffffffu, contrib, o);
    if (lane == 0) red[wid] = contrib;
    __syncthreads();
    if (tid == 0) g_part[blockIdx.x] = (red[0] + red[1]) + (red[2] + red[3]);
}

// ---------------------------------------------------------------------------
// Final deterministic reduction -> mean
// ---------------------------------------------------------------------------
__global__ __launch_bounds__(256) void finish_kernel(float* __restrict__ out)
{
    __shared__ float red[256];
    const int tid = threadIdx.x;
    red[tid] = g_part[tid] + g_part[tid + 256];
    __syncthreads();
    #pragma unroll
    for (int st = 128; st; st >>= 1) {
        if (tid < st) red[tid] += red[tid + st];
        __syncthreads();
    }
    if (tid == 0) out[0] = red[0] * (1.0f / NMROWS);
}

// ---------------------------------------------------------------------------
extern "C" void kernel_launch(void* const* d_in, const int* in_sizes, int n_in,
                              void* d_out, int out_size)
{
    const float* emb = (const float*)d_in[0];
    const float* w   = (const float*)d_in[1];
    float* out = (float*)d_out;

    cudaFuncSetAttribute(main_kernel, cudaFuncAttributeMaxDynamicSharedMemorySize,
                         SMEM_TOTAL);

    prologue_kernel<<<NSPK, 256>>>(emb);
    main_kernel<<<GBLK, 128, SMEM_TOTAL>>>(w);
    finish_kernel<<<1, 256>>>(out);
}

// round 4
// speedup vs baseline: 3.6707x; 1.2183x over previous
#include <cuda_runtime.h>
#include <cuda_bf16.h>
#include <cstdint>
#include <math.h>

// ---------------- problem constants ----------------
#define NSPK   1024
#define MUTT   32
#define DEMB   512
#define NMROWS (NSPK * MUTT)        // 32768

#define TM       128                // CTA row tile
#define TNB      128                // n-chunk width
#define NB_PER   2                  // n-chunks per CTA  (N-split x4)
#define NSPLIT   4
#define ITER_NB  24                 // 3 terms x 8 k64-chunks per n-chunk
#define NIT      (NB_PER * ITER_NB) // 48 iterations per CTA
#define GUNITS   ((NMROWS / TM) * NSPLIT)  // 1024 CTAs

#define A_BYTES  (TM * 128)         // 16 KB (128 rows x 64 bf16)
#define B_BYTES  (TNB * 128)        // 16 KB
#define STAGE    (A_BYTES + B_BYTES)            // 32 KB
#define SMEM_TOTAL (3 * STAGE)                  // 96 KB, 3-stage ring

// ---------------- device scratch ----------------
// A2: per row [hi(e) (512) | lo(e) (512)]  -> 64 MB
// B2: per spk [hi(C) (512) | lo(C) (512)]  -> 2 MB (L2-resident)
__device__ __align__(1024) __nv_bfloat16 g_A2[(size_t)NMROWS * 1024];
__device__ __align__(1024) __nv_bfloat16 g_B2[(size_t)NSPK * 1024];
__device__ float  g_dval[NMROWS];
__device__ float2 g_ms[(size_t)NMROWS * NSPLIT];   // per-row per-split (max, sumexp)
__device__ float  g_part[NMROWS / 256];            // 128 block partials

// ---------------- helpers ----------------
__device__ __forceinline__ uint32_t smem_u32(const void* p) {
    uint32_t a;
    asm("{ .reg .u64 t; cvta.to.shared.u64 t, %1; cvt.u32.u64 %0, t; }" : "=r"(a) : "l"(p));
    return a;
}
__device__ __forceinline__ void cp16(uint32_t s, const void* g) {
    asm volatile("cp.async.cg.shared.global [%0], [%1], 16;" :: "r"(s), "l"(g) : "memory");
}
__device__ __forceinline__ void ldsm4(uint32_t& r0, uint32_t& r1, uint32_t& r2, uint32_t& r3,
                                      uint32_t a) {
    asm volatile("ldmatrix.sync.aligned.m8n8.x4.shared.b16 {%0,%1,%2,%3}, [%4];"
                 : "=r"(r0), "=r"(r1), "=r"(r2), "=r"(r3) : "r"(a));
}
__device__ __forceinline__ void mma16816(float* c, uint32_t a0, uint32_t a1, uint32_t a2,
                                         uint32_t a3, uint32_t b0, uint32_t b1) {
    asm volatile(
        "mma.sync.aligned.m16n8k16.row.col.f32.bf16.bf16.f32 "
        "{%0,%1,%2,%3},{%4,%5,%6,%7},{%8,%9},{%0,%1,%2,%3};"
        : "+f"(c[0]), "+f"(c[1]), "+f"(c[2]), "+f"(c[3])
        : "r"(a0), "r"(a1), "r"(a2), "r"(a3), "r"(b0), "r"(b1));
}

// ---------------------------------------------------------------------------
// Prologue: per speaker — centroid, B2=[hi(C)|lo(C)], A2=[hi(e)|lo(e)],
// dval[r] = dot(e_r,S) + ||e_r||^2/31  (fp32 Kahan)
// ---------------------------------------------------------------------------
__global__ __launch_bounds__(256) void prologue_kernel(const float* __restrict__ emb)
{
    __shared__ float S[DEMB];
    const int n = blockIdx.x, tid = threadIdx.x;
    const float* base = emb + (size_t)n * MUTT * DEMB;

    for (int d = tid; d < DEMB; d += 256) {
        float s = 0.f;
        #pragma unroll
        for (int m = 0; m < MUTT; ++m) s += base[m * DEMB + d];
        S[d] = s;
        float cv = s * (1.0f / MUTT);
        __nv_bfloat16 hi = __float2bfloat16(cv);
        __nv_bfloat16 lo = __float2bfloat16(cv - __bfloat162float(hi));
        size_t o = (size_t)n * 1024 + d;
        g_B2[o] = hi; g_B2[o + 512] = lo;
    }
    __syncthreads();

    const int wid = tid >> 5, lane = tid & 31;
    #pragma unroll
    for (int rr = 0; rr < 4; ++rr) {
        const int m = wid + rr * 8;
        const float* e = base + m * DEMB;
        float dot = 0.f, cd = 0.f, nn = 0.f, cn = 0.f;
        for (int k = lane; k < DEMB; k += 32) {
            float ev = e[k];
            float x = ev * S[k];
            float y = x - cd; float t = dot + y; cd = (t - dot) - y; dot = t;
            float x2 = ev * ev;
            float y2 = x2 - cn; float t2 = nn + y2; cn = (t2 - nn) - y2; nn = t2;
        }
        #pragma unroll
        for (int o = 16; o; o >>= 1) {
            dot += __shfl_xor_sync(0xffffffffu, dot, o);
            nn  += __shfl_xor_sync(0xffffffffu, nn,  o);
        }
        if (lane == 0) g_dval[n * MUTT + m] = dot + nn * (1.0f / 31.0f);
    }

    for (int idx = tid; idx < MUTT * DEMB; idx += 256) {
        float x = base[idx];
        int m = idx >> 9, d = idx & (DEMB - 1);
        __nv_bfloat16 hi = __float2bfloat16(x);
        __nv_bfloat16 lo = __float2bfloat16(x - __bfloat162float(hi));
        size_t a = ((size_t)(n * MUTT + m)) * 1024 + d;
        g_A2[a] = hi; g_A2[a + 512] = lo;
    }
}

// ---------------------------------------------------------------------------
// Main: mma.sync bf16 GEMM + fused shifted online logsumexp.
// CTA = 128 rows x (2 n-chunks of 128). 8 warps, warp owns m16 x n128.
// 3 virtual K-terms over stored K=1024: (hi,hi), (lo,hi), (hi,lo).
// ---------------------------------------------------------------------------
__device__ __forceinline__ void load_tiles(int t, int m0, int nb0, uint32_t sb, int tid)
{
    const int nbl = t / ITER_NB, i = t - nbl * ITER_NB;
    const int term = i >> 3, k = i & 7;
    const int ka = (term == 1) ? (8 + k) : k;   // A k64-chunk within K=1024
    const int kb = (term == 2) ? (8 + k) : k;   // B k64-chunk within K=1024
    const int nb = nb0 + nbl;
    const uint32_t st = sb + (uint32_t)(t % 3) * STAGE;
    const char* gA = (const char*)g_A2 + (size_t)m0 * 2048 + (size_t)ka * 128;
    const char* gB = (const char*)g_B2 + (size_t)nb * TNB * 2048 + (size_t)kb * 128;
    #pragma unroll
    for (int j = 0; j < 4; ++j) {               // A: 1024 x 16B lanes
        int u = tid + j * 256;
        int r = u >> 3, c = u & 7;
        cp16(st + r * 128 + (((c ^ (r & 7))) << 4), gA + (size_t)r * 2048 + c * 16);
    }
    #pragma unroll
    for (int j = 0; j < 4; ++j) {               // B: 1024 x 16B lanes
        int u = tid + j * 256;
        int r = u >> 3, c = u & 7;
        cp16(st + A_BYTES + r * 128 + (((c ^ (r & 7))) << 4),
             gB + (size_t)r * 2048 + c * 16);
    }
}

__global__ __launch_bounds__(256, 2) void main_kernel(const float* __restrict__ wp)
{
    extern __shared__ __align__(128) char smem[];
    const uint32_t sb = smem_u32(smem);

    const int tid = threadIdx.x, wid = tid >> 5, lane = tid & 31;
    const int q = lane >> 2, r4 = lane & 3;
    const int unit = blockIdx.x;
    const int m0  = (unit >> 2) * TM;
    const int h   = unit & 3;
    const int nb0 = h * NB_PER;

    const float wv   = wp[0];
    const int   R0   = m0 + wid * 16 + q;        // rows R0 and R0+8
    const float wdv0 = wv * g_dval[R0];
    const float wdv1 = wv * g_dval[R0 + 8];
    const int   spkcol = R0 >> 5;

    const int lrow = lane & 15, lkoff = lane >> 4;

    float acc[16][4];
    float mM[2] = {-INFINITY, -INFINITY}, sS[2] = {0.f, 0.f};

    #pragma unroll
    for (int t = 0; t < 3; ++t) {
        load_tiles(t, m0, nb0, sb, tid);
        asm volatile("cp.async.commit_group;" ::: "memory");
    }

    for (int t = 0; t < NIT; ++t) {
        const int nbl = t / ITER_NB, i = t - nbl * ITER_NB;

        asm volatile("cp.async.wait_group 2;" ::: "memory");
        __syncthreads();

        if (i == 0) {
            #pragma unroll
            for (int j = 0; j < 16; ++j)
                #pragma unroll
                for (int e = 0; e < 4; ++e) acc[j][e] = 0.f;
        }

        const uint32_t st = sb + (uint32_t)(t % 3) * STAGE;
        #pragma unroll
        for (int ks = 0; ks < 4; ++ks) {
            uint32_t a0, a1, a2, a3;
            {
                int r = wid * 16 + lrow;
                int c = ks * 2 + lkoff;
                ldsm4(a0, a1, a2, a3, st + r * 128 + (((c ^ (r & 7))) << 4));
            }
            #pragma unroll
            for (int g = 0; g < 8; ++g) {
                uint32_t b0, b1, b2, b3;
                int r = g * 16 + lrow;
                int c = ks * 2 + lkoff;
                ldsm4(b0, b1, b2, b3,
                      st + A_BYTES + r * 128 + (((c ^ (r & 7))) << 4));
                mma16816(acc[2 * g + 0], a0, a1, a2, a3, b0, b2);
                mma16816(acc[2 * g + 1], a0, a1, a2, a3, b1, b3);
            }
        }

        if (i == ITER_NB - 1) {
            const int nb = nb0 + nbl;
            #pragma unroll
            for (int hh = 0; hh < 2; ++hh) {
                float m = mM[hh], s = sS[hh];
                const float wdv = hh ? wdv1 : wdv0;
                #pragma unroll
                for (int j = 0; j < 16; ++j) {
                    #pragma unroll
                    for (int e = 0; e < 2; ++e) {
                        const int col = nb * TNB + j * 8 + r4 * 2 + e;
                        if (col != spkcol) {
                            float v = fmaf(wv, acc[j][hh * 2 + e], -wdv);
                            if (v > m) { s = s * __expf(m - v) + 1.f; m = v; }
                            else { float d = v - m; if (d > -80.f) s += __expf(d); }
                        }
                    }
                }
                mM[hh] = m; sS[hh] = s;
            }
        }
        __syncthreads();

        if (t + 3 < NIT) load_tiles(t + 3, m0, nb0, sb, tid);
        asm volatile("cp.async.commit_group;" ::: "memory");
    }

    // merge the 4 lanes (r4 = 0..3) sharing each row, then store (m,s) partial
    #pragma unroll
    for (int hh = 0; hh < 2; ++hh) {
        float m = mM[hh], s = sS[hh];
        #pragma unroll
        for (int o = 1; o <= 2; o <<= 1) {
            float om = __shfl_xor_sync(0xffffffffu, m, o);
            float os = __shfl_xor_sync(0xffffffffu, s, o);
            float nm = fmaxf(m, om);
            s = s * __expf(m - nm) + os * __expf(om - nm);
            m = nm;
        }
        if (r4 == 0) {
            const int row = hh ? (R0 + 8) : R0;
            g_ms[(size_t)row * NSPLIT + h] = make_float2(m, s);
        }
    }
}

// ---------------------------------------------------------------------------
// Merge: combine 4 split partials + diagonal term -> per-row loss,
// deterministic per-block reduction (128 blocks x 256 rows).
// ---------------------------------------------------------------------------
__global__ __launch_bounds__(256) void merge_kernel()
{
    __shared__ float red[256];
    const int tid = threadIdx.x;
    const int r = blockIdx.x * 256 + tid;

    float2 p0 = g_ms[(size_t)r * 4 + 0];
    float2 p1 = g_ms[(size_t)r * 4 + 1];
    float2 p2 = g_ms[(size_t)r * 4 + 2];
    float2 p3 = g_ms[(size_t)r * 4 + 3];
    float m = fmaxf(fmaxf(p0.x, p1.x), fmaxf(p2.x, p3.x));
    m = fmaxf(m, 0.f);                      // diagonal term (shifted value 0)
    float s = __expf(-m)
            + p0.y * __expf(p0.x - m) + p1.y * __expf(p1.x - m)
            + p2.y * __expf(p2.x - m) + p3.y * __expf(p3.x - m);
    red[tid] = m + logf(s);
    __syncthreads();
    #pragma unroll
    for (int st = 128; st; st >>= 1) {
        if (tid < st) red[tid] += red[tid + st];
        __syncthreads();
    }
    if (tid == 0) g_part[blockIdx.x] = red[0];
}

__global__ __launch_bounds__(128) void finish_kernel(float* __restrict__ out)
{
    __shared__ float red[128];
    const int tid = threadIdx.x;
    red[tid] = g_part[tid];
    __syncthreads();
    #pragma unroll
    for (int st = 64; st; st >>= 1) {
        if (tid < st) red[tid] += red[tid + st];
        __syncthreads();
    }
    if (tid == 0) out[0] = red[0] * (1.0f / NMROWS);
}

// ---------------------------------------------------------------------------
extern "C" void kernel_launch(void* const* d_in, const int* in_sizes, int n_in,
                              void* d_out, int out_size)
{
    const float* emb = (const float*)d_in[0];
    const float* w   = (const float*)d_in[1];
    float* out = (float*)d_out;

    cudaFuncSetAttribute(main_kernel, cudaFuncAttributeMaxDynamicSharedMemorySize,
                         SMEM_TOTAL);

    prologue_kernel<<<NSPK, 256>>>(emb);
    main_kernel<<<GUNITS, 256, SMEM_TOTAL>>>(w);
    merge_kernel<<<NMROWS / 256, 256>>>();
    finish_kernel<<<1, 128>>>(out);
}

// round 5
// speedup vs baseline: 7.7775x; 2.1188x over previous
#include <cuda_runtime.h>
#include <cuda_bf16.h>
#include <cstdint>
#include <math.h>

// ---------------- problem constants ----------------
#define NSPK   1024
#define MUTT   32
#define DEMB   512
#define NMROWS (NSPK * MUTT)        // 32768

// filter GEMM tiling
#define TM       128
#define TNB      128
#define NB_PER   2                  // n-chunks per CTA (N-split x4)
#define NSPLIT   4
#define KITER    8                  // 8 x k64 = K512 (1-term bf16)
#define NIT      (NB_PER * KITER)   // 16
#define GUNITS   ((NMROWS / TM) * NSPLIT)  // 1024

#define A_BYTES  (TM * 128)         // 16 KB
#define B_BYTES  (TNB * 128)        // 16 KB
#define STAGE    (A_BYTES + B_BYTES)
#define SMEM_TOTAL (3 * STAGE)      // 96 KB

#define VTHRESH  (-50.0f)           // flag threshold (needed: -40; sigma~0.3)
#define CAP      (1u << 20)         // candidate capacity

// ---------------- device scratch ----------------
__device__ __align__(1024) __nv_bfloat16 g_A1[(size_t)NMROWS * DEMB]; // 32 MB
__device__ __align__(1024) __nv_bfloat16 g_B1[(size_t)NSPK * DEMB];   // 1 MB
__device__ __align__(1024) float g_S[(size_t)NSPK * DEMB];            // 2 MB sums
__device__ float    g_dval[NMROWS];
__device__ uint32_t g_cnt;
__device__ uint32_t g_cand[CAP];
__device__ double   g_rowsum[NMROWS];
__device__ float    g_part[NMROWS / 256];

// ---------------- helpers ----------------
__device__ __forceinline__ uint32_t smem_u32(const void* p) {
    uint32_t a;
    asm("{ .reg .u64 t; cvta.to.shared.u64 t, %1; cvt.u32.u64 %0, t; }" : "=r"(a) : "l"(p));
    return a;
}
__device__ __forceinline__ void cp16(uint32_t s, const void* g) {
    asm volatile("cp.async.cg.shared.global [%0], [%1], 16;" :: "r"(s), "l"(g) : "memory");
}
__device__ __forceinline__ void ldsm4(uint32_t& r0, uint32_t& r1, uint32_t& r2, uint32_t& r3,
                                      uint32_t a) {
    asm volatile("ldmatrix.sync.aligned.m8n8.x4.shared.b16 {%0,%1,%2,%3}, [%4];"
                 : "=r"(r0), "=r"(r1), "=r"(r2), "=r"(r3) : "r"(a));
}
__device__ __forceinline__ void mma16816(float* c, uint32_t a0, uint32_t a1, uint32_t a2,
                                         uint32_t a3, uint32_t b0, uint32_t b1) {
    asm volatile(
        "mma.sync.aligned.m16n8k16.row.col.f32.bf16.bf16.f32 "
        "{%0,%1,%2,%3},{%4,%5,%6,%7},{%8,%9},{%0,%1,%2,%3};"
        : "+f"(c[0]), "+f"(c[1]), "+f"(c[2]), "+f"(c[3])
        : "r"(a0), "r"(a1), "r"(a2), "r"(a3), "r"(b0), "r"(b1));
}

// ---------------------------------------------------------------------------
// Prologue (per speaker): S sums (fp32), B1 = bf16(C), A1 = bf16(e),
// dval (fp32 Kahan), zero counter/rowsums.
// ---------------------------------------------------------------------------
__global__ __launch_bounds__(256) void prologue_kernel(const float* __restrict__ emb)
{
    __shared__ float S[DEMB];
    const int n = blockIdx.x, tid = threadIdx.x;
    const float* base = emb + (size_t)n * MUTT * DEMB;

    if (n == 0 && tid == 0) g_cnt = 0;
    if (tid < MUTT) g_rowsum[n * MUTT + tid] = 0.0;

    for (int d = tid; d < DEMB; d += 256) {
        float s = 0.f;
        #pragma unroll
        for (int m = 0; m < MUTT; ++m) s += base[m * DEMB + d];
        S[d] = s;
        g_S[(size_t)n * DEMB + d] = s;
        g_B1[(size_t)n * DEMB + d] = __float2bfloat16(s * (1.0f / MUTT));
    }
    __syncthreads();

    const int wid = tid >> 5, lane = tid & 31;
    #pragma unroll
    for (int rr = 0; rr < 4; ++rr) {
        const int m = wid + rr * 8;
        const float* e = base + m * DEMB;
        float dot = 0.f, cd = 0.f, nn = 0.f, cn = 0.f;
        for (int k = lane; k < DEMB; k += 32) {
            float ev = e[k];
            float x = ev * S[k];
            float y = x - cd; float t = dot + y; cd = (t - dot) - y; dot = t;
            float x2 = ev * ev;
            float y2 = x2 - cn; float t2 = nn + y2; cn = (t2 - nn) - y2; nn = t2;
        }
        #pragma unroll
        for (int o = 16; o; o >>= 1) {
            dot += __shfl_xor_sync(0xffffffffu, dot, o);
            nn  += __shfl_xor_sync(0xffffffffu, nn,  o);
        }
        if (lane == 0) g_dval[n * MUTT + m] = dot + nn * (1.0f / 31.0f);
    }

    for (int idx = tid; idx < MUTT * DEMB; idx += 256)
        g_A1[(size_t)n * MUTT * DEMB + idx] = __float2bfloat16(base[idx]);
}

// ---------------------------------------------------------------------------
// Filter: 1-term bf16 GEMM (K=512); flag (row,col) with v > VTHRESH.
// CTA = 128 rows x 2 n-chunks. 8 warps, warp owns m16 x n128.
// ---------------------------------------------------------------------------
__device__ __forceinline__ void load_tiles(int t, int m0, int nb0, uint32_t sb, int tid)
{
    const int nbl = t >> 3, k = t & 7;
    const int nb = nb0 + nbl;
    const uint32_t st = sb + (uint32_t)(t % 3) * STAGE;
    const char* gA = (const char*)g_A1 + (size_t)m0 * 1024 + (size_t)k * 128;
    const char* gB = (const char*)g_B1 + (size_t)nb * TNB * 1024 + (size_t)k * 128;
    #pragma unroll
    for (int j = 0; j < 4; ++j) {
        int u = tid + j * 256;
        int r = u >> 3, c = u & 7;
        cp16(st + r * 128 + (((c ^ (r & 7))) << 4), gA + (size_t)r * 1024 + c * 16);
    }
    #pragma unroll
    for (int j = 0; j < 4; ++j) {
        int u = tid + j * 256;
        int r = u >> 3, c = u & 7;
        cp16(st + A_BYTES + r * 128 + (((c ^ (r & 7))) << 4),
             gB + (size_t)r * 1024 + c * 16);
    }
}

__global__ __launch_bounds__(256, 2) void filter_kernel(const float* __restrict__ wp)
{
    extern __shared__ __align__(128) char smem[];
    const uint32_t sb = smem_u32(smem);

    const int tid = threadIdx.x, wid = tid >> 5, lane = tid & 31;
    const int q = lane >> 2, r4 = lane & 3;
    const int unit = blockIdx.x;
    const int m0  = (unit >> 2) * TM;
    const int nb0 = (unit & 3) * NB_PER;

    const float wv   = wp[0];
    const int   R0   = m0 + wid * 16 + q;
    const float wdv0 = wv * g_dval[R0];
    const float wdv1 = wv * g_dval[R0 + 8];
    const int   spkcol = R0 >> 5;

    const int lrow = lane & 15, lkoff = lane >> 4;

    float acc[16][4];

    #pragma unroll
    for (int t = 0; t < 3; ++t) {
        load_tiles(t, m0, nb0, sb, tid);
        asm volatile("cp.async.commit_group;" ::: "memory");
    }

    for (int t = 0; t < NIT; ++t) {
        const int nbl = t >> 3, i = t & 7;

        asm volatile("cp.async.wait_group 2;" ::: "memory");
        __syncthreads();

        if (i == 0) {
            #pragma unroll
            for (int j = 0; j < 16; ++j)
                #pragma unroll
                for (int e = 0; e < 4; ++e) acc[j][e] = 0.f;
        }

        const uint32_t st = sb + (uint32_t)(t % 3) * STAGE;
        #pragma unroll
        for (int ks = 0; ks < 4; ++ks) {
            uint32_t a0, a1, a2, a3;
            {
                int r = wid * 16 + lrow;
                int c = ks * 2 + lkoff;
                ldsm4(a0, a1, a2, a3, st + r * 128 + (((c ^ (r & 7))) << 4));
            }
            #pragma unroll
            for (int g = 0; g < 8; ++g) {
                uint32_t b0, b1, b2, b3;
                int r = g * 16 + lrow;
                int c = ks * 2 + lkoff;
                ldsm4(b0, b1, b2, b3,
                      st + A_BYTES + r * 128 + (((c ^ (r & 7))) << 4));
                mma16816(acc[2 * g + 0], a0, a1, a2, a3, b0, b2);
                mma16816(acc[2 * g + 1], a0, a1, a2, a3, b1, b3);
            }
        }

        if (i == KITER - 1) {
            const int nb = nb0 + nbl;
            #pragma unroll
            for (int hh = 0; hh < 2; ++hh) {
                const float wdv = hh ? wdv1 : wdv0;
                const int row = hh ? (R0 + 8) : R0;
                #pragma unroll
                for (int j = 0; j < 16; ++j) {
                    #pragma unroll
                    for (int e = 0; e < 2; ++e) {
                        const int col = nb * TNB + j * 8 + r4 * 2 + e;
                        float v = fmaf(wv, acc[j][hh * 2 + e], -wdv);
                        if (v > VTHRESH && col != spkcol) {
                            uint32_t idx = atomicAdd(&g_cnt, 1u);
                            if (idx < CAP)
                                g_cand[idx] = ((uint32_t)row << 10) | (uint32_t)col;
                        }
                    }
                }
            }
        }
        __syncthreads();

        if (t + 3 < NIT) load_tiles(t + 3, m0, nb0, sb, tid);
        asm volatile("cp.async.commit_group;" ::: "memory");
    }
}

// ---------------------------------------------------------------------------
// Refine: one warp per candidate; exact fp64 logit; atomicAdd exp(v) per row.
// ---------------------------------------------------------------------------
__global__ __launch_bounds__(256) void refine_kernel(const float* __restrict__ emb,
                                                     const float* __restrict__ wp)
{
    const int lane = threadIdx.x & 31;
    const uint32_t gw = (blockIdx.x * blockDim.x + threadIdx.x) >> 5;
    const uint32_t nw = (gridDim.x * blockDim.x) >> 5;
    uint32_t cnt = g_cnt; if (cnt > CAP) cnt = CAP;
    const double wv = (double)wp[0];

    for (uint32_t i = gw; i < cnt; i += nw) {
        const uint32_t key = g_cand[i];
        const int row = key >> 10, col = key & 1023;
        const int spk = row >> 5;
        const float* e  = emb + (size_t)row * DEMB;
        const float* Sc = g_S + (size_t)col * DEMB;
        const float* Ss = g_S + (size_t)spk * DEMB;

        double dc = 0.0, ds = 0.0, nn = 0.0;
        #pragma unroll 4
        for (int k = lane; k < DEMB; k += 32) {
            const double ev = (double)e[k];
            dc = fma(ev, (double)Sc[k], dc);
            ds = fma(ev, (double)Ss[k], ds);
            nn = fma(ev, ev, nn);
        }
        #pragma unroll
        for (int o = 16; o; o >>= 1) {
            dc += __shfl_xor_sync(0xffffffffu, dc, o);
            ds += __shfl_xor_sync(0xffffffffu, ds, o);
            nn += __shfl_xor_sync(0xffffffffu, nn, o);
        }
        if (lane == 0) {
            const double dval = ds + nn * (1.0 / 31.0);
            const double v = wv * (dc * (1.0 / 32.0) - dval);
            atomicAdd(&g_rowsum[row], exp(v));
        }
    }
}

// ---------------------------------------------------------------------------
// Merge: per-row loss = log1p(rowsum); fixed-order block reduction.
// ---------------------------------------------------------------------------
__global__ __launch_bounds__(256) void merge_kernel()
{
    __shared__ float red[256];
    const int tid = threadIdx.x;
    const int r = blockIdx.x * 256 + tid;
    red[tid] = (float)log1p(g_rowsum[r]);
    __syncthreads();
    #pragma unroll
    for (int st = 128; st; st >>= 1) {
        if (tid < st) red[tid] += red[tid + st];
        __syncthreads();
    }
    if (tid == 0) g_part[blockIdx.x] = red[0];
}

__global__ __launch_bounds__(128) void finish_kernel(float* __restrict__ out)
{
    __shared__ float red[128];
    const int tid = threadIdx.x;
    red[tid] = g_part[tid];
    __syncthreads();
    #pragma unroll
    for (int st = 64; st; st >>= 1) {
        if (tid < st) red[tid] += red[tid + st];
        __syncthreads();
    }
    if (tid == 0) out[0] = red[0] * (1.0f / NMROWS);
}

// ---------------------------------------------------------------------------
extern "C" void kernel_launch(void* const* d_in, const int* in_sizes, int n_in,
                              void* d_out, int out_size)
{
    const float* emb = (const float*)d_in[0];
    const float* w   = (const float*)d_in[1];
    float* out = (float*)d_out;

    cudaFuncSetAttribute(filter_kernel, cudaFuncAttributeMaxDynamicSharedMemorySize,
                         SMEM_TOTAL);

    prologue_kernel<<<NSPK, 256>>>(emb);
    filter_kernel<<<GUNITS, 256, SMEM_TOTAL>>>(w);
    refine_kernel<<<256, 256>>>(emb, w);
    merge_kernel<<<NMROWS / 256, 256>>>();
    finish_kernel<<<1, 128>>>(out);
}